// round 7
// baseline (speedup 1.0000x reference)
#include <cuda_runtime.h>
#include <math.h>

// Problem constants
#define G_   64
#define NPG_ 256
#define EPG_ 4096
#define NN   16384       // total nodes
#define EE   262144      // total edges
#define HH   4
#define CC   64
#define HC   256
#define INC  256

// -------- scratch (static device globals; no allocation allowed) --------
__device__ __align__(16) float g_ohfeat[NN * 8];
__device__ __align__(16) float g_xp[NN * HC];
__device__ __align__(16) float g_al[NN * HH];
__device__ __align__(16) float g_ar[NN * HH];
__device__ __align__(16) float g_eeC[EE * HH];   // exp(logit - max), CSR-ordered: [slot*4 + h]
__device__ __align__(16) float g_inv[NN * HH];   // 1/(sum+eps) per (node, head)
__device__ int   g_cnt[NN];
__device__ int   g_off[NN];
__device__ int   g_srcL[EE];       // CSR: local src per slot

// -------- small weights staged in device globals (graph-capturable copy) --------
__device__ __align__(16) float g_watt_l[256];
__device__ __align__(16) float g_watt_r[256];
__device__ __align__(16) float g_wbias[256];
__device__ __align__(16) float g_wc1w[24];
__device__ __align__(16) float g_wc1b[8];
__device__ __align__(16) float g_wc2w[384];   // [16][8][3]
__device__ __align__(16) float g_wc2b[16];
__device__ __align__(16) float g_wfcw[128];   // [16][8]
__device__ __align__(16) float g_wfcb[8];

// ======================= weight copy =======================
__global__ void k_copyw(const float* __restrict__ att_l, const float* __restrict__ att_r,
                        const float* __restrict__ bias,
                        const float* __restrict__ c1w, const float* __restrict__ c1b,
                        const float* __restrict__ c2w, const float* __restrict__ c2b,
                        const float* __restrict__ fcw, const float* __restrict__ fcb) {
    int t = threadIdx.x;   // 256 threads, 1 block
    g_watt_l[t] = att_l[t];
    g_watt_r[t] = att_r[t];
    g_wbias[t]  = bias[t];
    if (t < 24)  g_wc1w[t] = c1w[t];
    if (t < 8)   g_wc1b[t] = c1b[t];
    if (t < 128) { g_wc2w[t] = c2w[t]; g_wc2w[t + 128] = c2w[t + 128]; }
    if (t < 128) g_wc2w[t + 256] = c2w[t + 256];
    if (t < 16)  g_wc2b[t] = c2b[t];
    if (t < 128) g_wfcw[t] = fcw[t];
    if (t < 8)   g_wfcb[t] = fcb[t];
}

// ======================= CSR build: hist + scan + scatter, one block per graph =======================
// adjs is INT32: [G, 2, EPG]
__global__ void k_csr(const int* __restrict__ adjs) {
    __shared__ int cnt[256];
    __shared__ int scn[256];
    __shared__ int cur[256];
    const int g = blockIdx.x, t = threadIdx.x;

    cnt[t] = 0;
    __syncthreads();

    const int* srcp = adjs + (long long)g * 8192;
    const int* dstp = srcp + 4096;

    int dl[16];
    #pragma unroll
    for (int i = 0; i < 16; i++) {
        dl[i] = dstp[i * 256 + t];
        atomicAdd(&cnt[dl[i]], 1);
    }
    __syncthreads();

    // inclusive Hillis-Steele scan in shared
    int v = cnt[t];
    scn[t] = v;
    __syncthreads();
    for (int o = 1; o < 256; o <<= 1) {
        int add = (t >= o) ? scn[t - o] : 0;
        __syncthreads();
        scn[t] += add;
        __syncthreads();
    }
    int excl = scn[t] - v;
    g_cnt[g * 256 + t] = v;
    g_off[g * 256 + t] = excl;
    cur[t] = excl;
    __syncthreads();

    #pragma unroll
    for (int i = 0; i < 16; i++) {
        int srcl = srcp[i * 256 + t];
        int pos = atomicAdd(&cur[dl[i]], 1);
        g_srcL[g * 4096 + pos] = srcl;
    }
}

// ======================= sort + conv pipe =======================
// one block (256 threads) per node
__global__ void k_sortconv(const float* __restrict__ oh) {
    __shared__ float s[256];
    __shared__ float c1[8][258];     // halo-padded: c1[c][l+1]
    __shared__ float sums[16];
    __shared__ float w_c1w[24], w_c1b[8], w_c2w[384], w_c2b[16], w_fcw[128], w_fcb[8];

    const int n = blockIdx.x;
    const int t = threadIdx.x;

    // stage weights into shared (broadcast reads in the hot loops)
    if (t < 24)  w_c1w[t] = g_wc1w[t];
    if (t < 8)   { w_c1b[t] = g_wc1b[t]; w_fcb[t] = g_wfcb[t]; }
    if (t < 128) { w_c2w[t] = g_wc2w[t]; w_c2w[t + 128] = g_wc2w[t + 128]; }
    if (t >= 128 && t < 256) w_c2w[t + 128] = g_wc2w[t + 128];
    if (t < 16)  { w_c2b[t] = g_wc2b[t]; }
    if (t < 128) w_fcw[t] = g_wfcw[t];

    s[t] = oh[(long long)n * 256 + t];

    // bitonic sort ascending
    for (int k = 2; k <= 256; k <<= 1) {
        for (int j = k >> 1; j > 0; j >>= 1) {
            __syncthreads();
            int ixj = t ^ j;
            if (ixj > t) {
                float a = s[t], b = s[ixj];
                bool swap = ((t & k) == 0) ? (a > b) : (a < b);
                if (swap) { s[t] = b; s[ixj] = a; }
            }
        }
    }
    __syncthreads();

    float xm  = (t > 0)   ? s[t - 1] : 0.f;
    float x0  = s[t];
    float xp1 = (t < 255) ? s[t + 1] : 0.f;

    #pragma unroll
    for (int c = 0; c < 8; c++) {
        float v = w_c1b[c] + w_c1w[c*3+0]*xm + w_c1w[c*3+1]*x0 + w_c1w[c*3+2]*xp1;
        c1[c][t + 1] = fmaxf(v, 0.f);
    }
    if (t < 8)  { c1[t][0] = 0.f; c1[t][257] = 0.f; }
    if (t < 16) sums[t] = 0.f;
    __syncthreads();

    // conv2 (8->16, k=3) at position l = t, all 16 output channels
    float acc[16];
    #pragma unroll
    for (int co = 0; co < 16; co++) acc[co] = w_c2b[co];
    #pragma unroll
    for (int ci = 0; ci < 8; ci++) {
        float hm = c1[ci][t];
        float h0 = c1[ci][t + 1];
        float hp = c1[ci][t + 2];
        #pragma unroll
        for (int co = 0; co < 16; co++) {
            const int w = co * 24 + ci * 3;
            acc[co] += w_c2w[w] * hm + w_c2w[w + 1] * h0 + w_c2w[w + 2] * hp;
        }
    }

    // relu + mean over L (warp reduce then smem accumulate)
    #pragma unroll
    for (int co = 0; co < 16; co++) {
        float v = fmaxf(acc[co], 0.f);
        #pragma unroll
        for (int o = 16; o > 0; o >>= 1) v += __shfl_down_sync(0xffffffffu, v, o);
        if ((t & 31) == 0) atomicAdd(&sums[co], v);
    }
    __syncthreads();

    // fc: [16] -> [8]
    if (t < 8) {
        float r = w_fcb[t];
        #pragma unroll
        for (int c = 0; c < 16; c++)
            r += (sums[c] * (1.f / 256.f)) * w_fcw[c * 8 + t];
        g_ohfeat[n * 8 + t] = r;
    }
}

// ======================= projection GEMM =======================
// xp = concat([x, oh_feat]) @ lin_w   : [16384 x 264] @ [264 x 256]
// block tile 64x64, 256 threads (16x16), 4x4 per thread, K-chunk 8
__global__ void k_gemm(const float* __restrict__ x, const float* __restrict__ lw) {
    __shared__ float As[8][64];
    __shared__ float Bs[8][64];

    const int tid = threadIdx.x;
    const int bm = blockIdx.x * 64;
    const int bn = blockIdx.y * 64;
    const int tx = tid & 15;
    const int ty = tid >> 4;

    const int lm = tid >> 2;           // A-load row 0..63
    const int lk = (tid & 3) * 2;      // A-load k   {0,2,4,6}
    const int bk = tid >> 5;           // B-load k   0..7
    const int bc = (tid & 31) * 2;     // B-load col

    float acc[4][4];
    #pragma unroll
    for (int i = 0; i < 4; i++)
        #pragma unroll
        for (int j = 0; j < 4; j++) acc[i][j] = 0.f;

    for (int k0 = 0; k0 < 264; k0 += 8) {
        const int grow = bm + lm;
        #pragma unroll
        for (int u = 0; u < 2; u++) {
            int kk = k0 + lk + u;
            float v = (kk < 256) ? x[(long long)grow * 256 + kk]
                                 : g_ohfeat[grow * 8 + (kk - 256)];
            As[lk + u][lm] = v;
        }
        {
            const float2 bv = *(const float2*)&lw[(long long)(k0 + bk) * 256 + bn + bc];
            Bs[bk][bc] = bv.x; Bs[bk][bc + 1] = bv.y;
        }
        __syncthreads();
        #pragma unroll
        for (int kk = 0; kk < 8; kk++) {
            float4 a4 = *(const float4*)&As[kk][ty * 4];
            float4 b4 = *(const float4*)&Bs[kk][tx * 4];
            float a[4] = {a4.x, a4.y, a4.z, a4.w};
            float b[4] = {b4.x, b4.y, b4.z, b4.w};
            #pragma unroll
            for (int i = 0; i < 4; i++)
                #pragma unroll
                for (int j = 0; j < 4; j++) acc[i][j] += a[i] * b[j];
        }
        __syncthreads();
    }

    #pragma unroll
    for (int i = 0; i < 4; i++) {
        int r = bm + ty * 4 + i;
        float4 v = {acc[i][0], acc[i][1], acc[i][2], acc[i][3]};
        *(float4*)&g_xp[(long long)r * 256 + bn + tx * 4] = v;
    }
}

// ======================= attention coefficients =======================
__global__ void k_alpha() {
    int i = blockIdx.x * 256 + threadIdx.x;   // over N*H
    if (i >= NN * HH) return;
    int n = i >> 2, h = i & 3;
    const float4* row = (const float4*)&g_xp[(long long)n * 256 + h * 64];
    const float4* attl = (const float4*)g_watt_l;
    const float4* attr = (const float4*)g_watt_r;
    float sl = 0.f, sr = 0.f;
    #pragma unroll
    for (int q = 0; q < 16; q++) {
        float4 v = row[q];
        float4 l = attl[h * 16 + q];
        float4 r = attr[h * 16 + q];
        sl += v.x * l.x + v.y * l.y + v.z * l.z + v.w * l.w;
        sr += v.x * r.x + v.y * r.y + v.z * r.z + v.w * r.w;
    }
    g_al[i] = sl;
    g_ar[i] = sr;
}

// ======================= softmax over CSR segments =======================
// one warp per node, all 4 heads per lane: srcL read once, al as LDG.128,
// eeC written as STG.128.
__global__ void k_softmax() {
    int wid = (blockIdx.x * blockDim.x + threadIdx.x) >> 5;   // global warp id = node
    int lane = threadIdx.x & 31;
    if (wid >= NN) return;
    const int node = wid;
    const int g = node >> 8;
    const int beg = g * 4096 + g_off[node];
    const int cnt = g_cnt[node];
    const float4 ar = *(const float4*)&g_ar[node * 4];

    // pass 1: per-head max
    float m0 = -INFINITY, m1 = -INFINITY, m2 = -INFINITY, m3 = -INFINITY;
    for (int it = lane; it < cnt; it += 32) {
        int src = g * 256 + g_srcL[beg + it];
        float4 al = *(const float4*)&g_al[src * 4];
        float v0 = al.x + ar.x; v0 = (v0 > 0.f) ? v0 : 0.2f * v0;
        float v1 = al.y + ar.y; v1 = (v1 > 0.f) ? v1 : 0.2f * v1;
        float v2 = al.z + ar.z; v2 = (v2 > 0.f) ? v2 : 0.2f * v2;
        float v3 = al.w + ar.w; v3 = (v3 > 0.f) ? v3 : 0.2f * v3;
        m0 = fmaxf(m0, v0); m1 = fmaxf(m1, v1);
        m2 = fmaxf(m2, v2); m3 = fmaxf(m3, v3);
    }
    #pragma unroll
    for (int o = 16; o > 0; o >>= 1) {
        m0 = fmaxf(m0, __shfl_xor_sync(0xffffffffu, m0, o));
        m1 = fmaxf(m1, __shfl_xor_sync(0xffffffffu, m1, o));
        m2 = fmaxf(m2, __shfl_xor_sync(0xffffffffu, m2, o));
        m3 = fmaxf(m3, __shfl_xor_sync(0xffffffffu, m3, o));
    }

    // pass 2: exp + sum, vectorized CSR-ordered store
    float s0 = 0.f, s1 = 0.f, s2 = 0.f, s3 = 0.f;
    for (int it = lane; it < cnt; it += 32) {
        int src = g * 256 + g_srcL[beg + it];
        float4 al = *(const float4*)&g_al[src * 4];
        float v0 = al.x + ar.x; v0 = (v0 > 0.f) ? v0 : 0.2f * v0;
        float v1 = al.y + ar.y; v1 = (v1 > 0.f) ? v1 : 0.2f * v1;
        float v2 = al.z + ar.z; v2 = (v2 > 0.f) ? v2 : 0.2f * v2;
        float v3 = al.w + ar.w; v3 = (v3 > 0.f) ? v3 : 0.2f * v3;
        float4 ev;
        ev.x = __expf(v0 - m0); ev.y = __expf(v1 - m1);
        ev.z = __expf(v2 - m2); ev.w = __expf(v3 - m3);
        *(float4*)&g_eeC[(beg + it) * 4] = ev;
        s0 += ev.x; s1 += ev.y; s2 += ev.z; s3 += ev.w;
    }
    #pragma unroll
    for (int o = 16; o > 0; o >>= 1) {
        s0 += __shfl_xor_sync(0xffffffffu, s0, o);
        s1 += __shfl_xor_sync(0xffffffffu, s1, o);
        s2 += __shfl_xor_sync(0xffffffffu, s2, o);
        s3 += __shfl_xor_sync(0xffffffffu, s3, o);
    }

    if (lane == 0) {
        float4 inv;
        inv.x = 1.f / (s0 + 1e-16f);
        inv.y = 1.f / (s1 + 1e-16f);
        inv.z = 1.f / (s2 + 1e-16f);
        inv.w = 1.f / (s3 + 1e-16f);
        *(float4*)&g_inv[node * 4] = inv;
    }
}

// ======================= onehot aggregation (gather form, MLP-unrolled) =======================
// grid = G*8 blocks; block covers (graph g, 32-col chunk); 256 thr = 32 dst x 8 f4
__global__ void k_ohagg(const float* __restrict__ oh, float* __restrict__ out) {
    int g = blockIdx.x >> 3;
    int chunk = blockIdx.x & 7;
    int t = threadIdx.x;
    int q = t & 7;             // float4 within chunk
    int dsub = t >> 3;         // 0..31
    int colf4 = chunk * 8 + q; // 0..63

    const float4* ohg = (const float4*)(oh + (long long)g * 65536);
    float4* og = (float4*)(out + (long long)g * 65536);

    for (int d0 = 0; d0 < 256; d0 += 32) {
        int dst = d0 + dsub;
        int node = g * 256 + dst;
        float4 acc = ohg[dst * 64 + colf4];    // residual
        int beg = g * 4096 + g_off[node];
        int cnt = g_cnt[node];
        int it = 0;
        for (; it + 4 <= cnt; it += 4) {
            int s0 = g_srcL[beg + it];
            int s1 = g_srcL[beg + it + 1];
            int s2 = g_srcL[beg + it + 2];
            int s3 = g_srcL[beg + it + 3];
            float4 v0 = ohg[s0 * 64 + colf4];
            float4 v1 = ohg[s1 * 64 + colf4];
            float4 v2 = ohg[s2 * 64 + colf4];
            float4 v3 = ohg[s3 * 64 + colf4];
            acc.x += v0.x + v1.x + v2.x + v3.x;
            acc.y += v0.y + v1.y + v2.y + v3.y;
            acc.z += v0.z + v1.z + v2.z + v3.z;
            acc.w += v0.w + v1.w + v2.w + v3.w;
        }
        for (; it < cnt; it++) {
            int srcl = g_srcL[beg + it];
            float4 v = ohg[srcl * 64 + colf4];
            acc.x += v.x; acc.y += v.y; acc.z += v.z; acc.w += v.w;
        }
        og[dst * 64 + colf4] = acc;
    }
}

// ======================= attention aggregation (gather form, MLP-unrolled) =======================
__global__ void k_attagg(float* __restrict__ out) {
    int g = blockIdx.x >> 3;
    int chunk = blockIdx.x & 7;
    int h = chunk >> 1;              // head = (chunk*32)/64
    int t = threadIdx.x;
    int q = t & 7;
    int dsub = t >> 3;
    int colf4 = chunk * 8 + q;       // float4 column 0..63 (col = colf4*4)

    const float4* xpg = (const float4*)&g_xp[(long long)g * 256 * 256];

    for (int d0 = 0; d0 < 256; d0 += 32) {
        int dst = d0 + dsub;
        int node = g * 256 + dst;
        float inv = g_inv[node * 4 + h];
        float4 acc = {0.f, 0.f, 0.f, 0.f};
        int beg = g * 4096 + g_off[node];
        int cnt = g_cnt[node];
        int it = 0;
        for (; it + 4 <= cnt; it += 4) {
            int s0 = g_srcL[beg + it];
            int s1 = g_srcL[beg + it + 1];
            int s2 = g_srcL[beg + it + 2];
            int s3 = g_srcL[beg + it + 3];
            float w0 = g_eeC[(beg + it) * 4 + h];
            float w1 = g_eeC[(beg + it + 1) * 4 + h];
            float w2 = g_eeC[(beg + it + 2) * 4 + h];
            float w3 = g_eeC[(beg + it + 3) * 4 + h];
            float4 v0 = xpg[s0 * 64 + colf4];
            float4 v1 = xpg[s1 * 64 + colf4];
            float4 v2 = xpg[s2 * 64 + colf4];
            float4 v3 = xpg[s3 * 64 + colf4];
            acc.x += w0 * v0.x + w1 * v1.x + w2 * v2.x + w3 * v3.x;
            acc.y += w0 * v0.y + w1 * v1.y + w2 * v2.y + w3 * v3.y;
            acc.z += w0 * v0.z + w1 * v1.z + w2 * v2.z + w3 * v3.z;
            acc.w += w0 * v0.w + w1 * v1.w + w2 * v2.w + w3 * v3.w;
        }
        for (; it < cnt; it++) {
            int srcl = g_srcL[beg + it];
            float w = g_eeC[(beg + it) * 4 + h];
            float4 v = xpg[srcl * 64 + colf4];
            acc.x += w * v.x; acc.y += w * v.y; acc.z += w * v.z; acc.w += w * v.w;
        }
        float4 b = *(const float4*)&g_wbias[colf4 * 4];
        acc.x = acc.x * inv + b.x;
        acc.y = acc.y * inv + b.y;
        acc.z = acc.z * inv + b.z;
        acc.w = acc.w * inv + b.w;
        *(float4*)&out[(long long)node * 256 + colf4 * 4] = acc;
    }
}

// ======================= launch =======================
extern "C" void kernel_launch(void* const* d_in, const int* in_sizes, int n_in,
                              void* d_out, int out_size) {
    const float* x    = (const float*)d_in[0];
    const float* oh   = (const float*)d_in[1];
    const int*   adjs = (const int*)d_in[2];       // int32 (JAX default x64-disabled)
    const float* lw   = (const float*)d_in[3];

    float* out   = (float*)d_out;
    float* x_out = out;                      // [N, 256]
    float* noh   = out + (size_t)NN * HC;    // [G, 256, 256]

    k_copyw<<<1, 256>>>((const float*)d_in[4], (const float*)d_in[5], (const float*)d_in[6],
                        (const float*)d_in[7], (const float*)d_in[8], (const float*)d_in[9],
                        (const float*)d_in[10], (const float*)d_in[11], (const float*)d_in[12]);
    k_csr     <<<G_, 256>>>(adjs);
    k_sortconv<<<NN, 256>>>(oh);
    k_gemm    <<<dim3(256, 4), 256>>>(x, lw);
    k_alpha   <<<256, 256>>>();
    k_softmax <<<NN / 8, 256>>>();           // 8 warps/block, one warp per node (4 heads/lane)
    k_ohagg   <<<512, 256>>>(oh, noh);
    k_attagg  <<<512, 256>>>(x_out);
}

// round 8
// speedup vs baseline: 1.0240x; 1.0240x over previous
#include <cuda_runtime.h>
#include <math.h>

// Problem constants
#define G_   64
#define NPG_ 256
#define EPG_ 4096
#define NN   16384       // total nodes
#define EE   262144      // total edges
#define HH   4
#define CC   64
#define HC   256
#define INC  256

// -------- scratch (static device globals; no allocation allowed) --------
__device__ __align__(16) float g_ohfeat[NN * 8];
__device__ __align__(16) float g_xp[NN * HC];
__device__ __align__(16) float g_al[NN * HH];
__device__ __align__(16) float g_ar[NN * HH];
__device__ __align__(16) float g_eeC[EE * HH];   // exp(logit - max), CSR-ordered: [slot*4 + h]
__device__ __align__(16) float g_inv[NN * HH];   // 1/(sum+eps) per (node, head)
__device__ int   g_cnt[NN];
__device__ int   g_off[NN];
__device__ __align__(16) int g_srcL[EE];         // CSR: local src per slot

// -------- small weights staged in device globals (graph-capturable copy) --------
__device__ __align__(16) float g_watt_l[256];
__device__ __align__(16) float g_watt_r[256];
__device__ __align__(16) float g_wbias[256];
__device__ __align__(16) float g_wc1w[24];
__device__ __align__(16) float g_wc1b[8];
__device__ __align__(16) float g_wc2w[384];   // [16][8][3]
__device__ __align__(16) float g_wc2b[16];
__device__ __align__(16) float g_wfcw[128];   // [16][8]
__device__ __align__(16) float g_wfcb[8];

// ======================= weight copy =======================
__global__ void k_copyw(const float* __restrict__ att_l, const float* __restrict__ att_r,
                        const float* __restrict__ bias,
                        const float* __restrict__ c1w, const float* __restrict__ c1b,
                        const float* __restrict__ c2w, const float* __restrict__ c2b,
                        const float* __restrict__ fcw, const float* __restrict__ fcb) {
    int t = threadIdx.x;   // 256 threads, 1 block
    g_watt_l[t] = att_l[t];
    g_watt_r[t] = att_r[t];
    g_wbias[t]  = bias[t];
    if (t < 24)  g_wc1w[t] = c1w[t];
    if (t < 8)   g_wc1b[t] = c1b[t];
    if (t < 128) { g_wc2w[t] = c2w[t]; g_wc2w[t + 128] = c2w[t + 128]; }
    if (t < 128) g_wc2w[t + 256] = c2w[t + 256];
    if (t < 16)  g_wc2b[t] = c2b[t];
    if (t < 128) g_wfcw[t] = fcw[t];
    if (t < 8)   g_wfcb[t] = fcb[t];
}

// ======================= CSR build: hist + scan + scatter, one block per graph =======================
// adjs is INT32: [G, 2, EPG]
__global__ void k_csr(const int* __restrict__ adjs) {
    __shared__ int cnt[256];
    __shared__ int scn[256];
    __shared__ int cur[256];
    const int g = blockIdx.x, t = threadIdx.x;

    cnt[t] = 0;
    __syncthreads();

    const int* srcp = adjs + (long long)g * 8192;
    const int* dstp = srcp + 4096;

    int dl[16];
    #pragma unroll
    for (int i = 0; i < 16; i++) {
        dl[i] = dstp[i * 256 + t];
        atomicAdd(&cnt[dl[i]], 1);
    }
    __syncthreads();

    // inclusive Hillis-Steele scan in shared
    int v = cnt[t];
    scn[t] = v;
    __syncthreads();
    for (int o = 1; o < 256; o <<= 1) {
        int add = (t >= o) ? scn[t - o] : 0;
        __syncthreads();
        scn[t] += add;
        __syncthreads();
    }
    int excl = scn[t] - v;
    g_cnt[g * 256 + t] = v;
    g_off[g * 256 + t] = excl;
    cur[t] = excl;
    __syncthreads();

    #pragma unroll
    for (int i = 0; i < 16; i++) {
        int srcl = srcp[i * 256 + t];
        int pos = atomicAdd(&cur[dl[i]], 1);
        g_srcL[g * 4096 + pos] = srcl;
    }
}

// ======================= sort + conv pipe =======================
// one block (256 threads) per node
__global__ void k_sortconv(const float* __restrict__ oh) {
    __shared__ float s[256];
    __shared__ float c1[8][258];     // halo-padded: c1[c][l+1]
    __shared__ float sums[16];
    __shared__ float w_c1w[24], w_c1b[8], w_c2w[384], w_c2b[16], w_fcw[128], w_fcb[8];

    const int n = blockIdx.x;
    const int t = threadIdx.x;

    // stage weights into shared (broadcast reads in the hot loops)
    if (t < 24)  w_c1w[t] = g_wc1w[t];
    if (t < 8)   { w_c1b[t] = g_wc1b[t]; w_fcb[t] = g_wfcb[t]; }
    if (t < 128) { w_c2w[t] = g_wc2w[t]; w_c2w[t + 128] = g_wc2w[t + 128]; }
    if (t >= 128 && t < 256) w_c2w[t + 128] = g_wc2w[t + 128];
    if (t < 16)  { w_c2b[t] = g_wc2b[t]; }
    if (t < 128) w_fcw[t] = g_wfcw[t];

    s[t] = oh[(long long)n * 256 + t];

    // bitonic sort ascending
    for (int k = 2; k <= 256; k <<= 1) {
        for (int j = k >> 1; j > 0; j >>= 1) {
            __syncthreads();
            int ixj = t ^ j;
            if (ixj > t) {
                float a = s[t], b = s[ixj];
                bool swap = ((t & k) == 0) ? (a > b) : (a < b);
                if (swap) { s[t] = b; s[ixj] = a; }
            }
        }
    }
    __syncthreads();

    float xm  = (t > 0)   ? s[t - 1] : 0.f;
    float x0  = s[t];
    float xp1 = (t < 255) ? s[t + 1] : 0.f;

    #pragma unroll
    for (int c = 0; c < 8; c++) {
        float v = w_c1b[c] + w_c1w[c*3+0]*xm + w_c1w[c*3+1]*x0 + w_c1w[c*3+2]*xp1;
        c1[c][t + 1] = fmaxf(v, 0.f);
    }
    if (t < 8)  { c1[t][0] = 0.f; c1[t][257] = 0.f; }
    if (t < 16) sums[t] = 0.f;
    __syncthreads();

    // conv2 (8->16, k=3) at position l = t, all 16 output channels
    float acc[16];
    #pragma unroll
    for (int co = 0; co < 16; co++) acc[co] = w_c2b[co];
    #pragma unroll
    for (int ci = 0; ci < 8; ci++) {
        float hm = c1[ci][t];
        float h0 = c1[ci][t + 1];
        float hp = c1[ci][t + 2];
        #pragma unroll
        for (int co = 0; co < 16; co++) {
            const int w = co * 24 + ci * 3;
            acc[co] += w_c2w[w] * hm + w_c2w[w + 1] * h0 + w_c2w[w + 2] * hp;
        }
    }

    // relu + mean over L (warp reduce then smem accumulate)
    #pragma unroll
    for (int co = 0; co < 16; co++) {
        float v = fmaxf(acc[co], 0.f);
        #pragma unroll
        for (int o = 16; o > 0; o >>= 1) v += __shfl_down_sync(0xffffffffu, v, o);
        if ((t & 31) == 0) atomicAdd(&sums[co], v);
    }
    __syncthreads();

    // fc: [16] -> [8]
    if (t < 8) {
        float r = w_fcb[t];
        #pragma unroll
        for (int c = 0; c < 16; c++)
            r += (sums[c] * (1.f / 256.f)) * w_fcw[c * 8 + t];
        g_ohfeat[n * 8 + t] = r;
    }
}

// ======================= projection GEMM =======================
// xp = concat([x, oh_feat]) @ lin_w : [16384 x 264] @ [264 x 256]
// 128x128 block tile, 256 threads (16x16), 8x8 per thread, K-chunk 8
__global__ void k_gemm(const float* __restrict__ x, const float* __restrict__ lw) {
    __shared__ float As[8][128];
    __shared__ float Bs[8][128];

    const int tid = threadIdx.x;
    const int bm = blockIdx.x * 128;
    const int bn = blockIdx.y * 128;
    const int tx = tid & 15;           // 0..15 -> 8-col group
    const int ty = tid >> 4;           // 0..15 -> 8-row group

    const int arow = tid >> 1;         // 0..127
    const int ak4  = (tid & 1) * 4;    // {0,4}
    const int bk   = tid >> 5;         // 0..7
    const int bcol = (tid & 31) * 4;   // 0..124

    float acc[8][8];
    #pragma unroll
    for (int i = 0; i < 8; i++)
        #pragma unroll
        for (int j = 0; j < 8; j++) acc[i][j] = 0.f;

    const int grow = bm + arow;

    for (int k0 = 0; k0 < 264; k0 += 8) {
        float4 av;
        if (k0 < 256) av = *(const float4*)&x[(long long)grow * 256 + k0 + ak4];
        else          av = *(const float4*)&g_ohfeat[grow * 8 + ak4];
        As[ak4 + 0][arow] = av.x;
        As[ak4 + 1][arow] = av.y;
        As[ak4 + 2][arow] = av.z;
        As[ak4 + 3][arow] = av.w;
        *(float4*)&Bs[bk][bcol] = *(const float4*)&lw[(long long)(k0 + bk) * 256 + bn + bcol];
        __syncthreads();

        #pragma unroll
        for (int kk = 0; kk < 8; kk++) {
            float4 a0 = *(const float4*)&As[kk][ty * 8];
            float4 a1 = *(const float4*)&As[kk][ty * 8 + 4];
            float4 b0 = *(const float4*)&Bs[kk][tx * 8];
            float4 b1 = *(const float4*)&Bs[kk][tx * 8 + 4];
            float a[8] = {a0.x, a0.y, a0.z, a0.w, a1.x, a1.y, a1.z, a1.w};
            float b[8] = {b0.x, b0.y, b0.z, b0.w, b1.x, b1.y, b1.z, b1.w};
            #pragma unroll
            for (int i = 0; i < 8; i++)
                #pragma unroll
                for (int j = 0; j < 8; j++) acc[i][j] += a[i] * b[j];
        }
        __syncthreads();
    }

    #pragma unroll
    for (int i = 0; i < 8; i++) {
        int r = bm + ty * 8 + i;
        float4 v0 = {acc[i][0], acc[i][1], acc[i][2], acc[i][3]};
        float4 v1 = {acc[i][4], acc[i][5], acc[i][6], acc[i][7]};
        *(float4*)&g_xp[(long long)r * 256 + bn + tx * 8]     = v0;
        *(float4*)&g_xp[(long long)r * 256 + bn + tx * 8 + 4] = v1;
    }
}

// ======================= attention coefficients =======================
__global__ void k_alpha() {
    int i = blockIdx.x * 256 + threadIdx.x;   // over N*H
    if (i >= NN * HH) return;
    int n = i >> 2, h = i & 3;
    const float4* row = (const float4*)&g_xp[(long long)n * 256 + h * 64];
    const float4* attl = (const float4*)g_watt_l;
    const float4* attr = (const float4*)g_watt_r;
    float sl = 0.f, sr = 0.f;
    #pragma unroll
    for (int q = 0; q < 16; q++) {
        float4 v = row[q];
        float4 l = attl[h * 16 + q];
        float4 r = attr[h * 16 + q];
        sl += v.x * l.x + v.y * l.y + v.z * l.z + v.w * l.w;
        sr += v.x * r.x + v.y * r.y + v.z * r.z + v.w * r.w;
    }
    g_al[i] = sl;
    g_ar[i] = sr;
}

// ======================= softmax over CSR segments =======================
// one warp per node, all 4 heads per lane
__global__ void k_softmax() {
    int wid = (blockIdx.x * blockDim.x + threadIdx.x) >> 5;   // global warp id = node
    int lane = threadIdx.x & 31;
    if (wid >= NN) return;
    const int node = wid;
    const int g = node >> 8;
    const int beg = g * 4096 + g_off[node];
    const int cnt = g_cnt[node];
    const float4 ar = *(const float4*)&g_ar[node * 4];

    float m0 = -INFINITY, m1 = -INFINITY, m2 = -INFINITY, m3 = -INFINITY;
    for (int it = lane; it < cnt; it += 32) {
        int src = g * 256 + g_srcL[beg + it];
        float4 al = *(const float4*)&g_al[src * 4];
        float v0 = al.x + ar.x; v0 = (v0 > 0.f) ? v0 : 0.2f * v0;
        float v1 = al.y + ar.y; v1 = (v1 > 0.f) ? v1 : 0.2f * v1;
        float v2 = al.z + ar.z; v2 = (v2 > 0.f) ? v2 : 0.2f * v2;
        float v3 = al.w + ar.w; v3 = (v3 > 0.f) ? v3 : 0.2f * v3;
        m0 = fmaxf(m0, v0); m1 = fmaxf(m1, v1);
        m2 = fmaxf(m2, v2); m3 = fmaxf(m3, v3);
    }
    #pragma unroll
    for (int o = 16; o > 0; o >>= 1) {
        m0 = fmaxf(m0, __shfl_xor_sync(0xffffffffu, m0, o));
        m1 = fmaxf(m1, __shfl_xor_sync(0xffffffffu, m1, o));
        m2 = fmaxf(m2, __shfl_xor_sync(0xffffffffu, m2, o));
        m3 = fmaxf(m3, __shfl_xor_sync(0xffffffffu, m3, o));
    }

    float s0 = 0.f, s1 = 0.f, s2 = 0.f, s3 = 0.f;
    for (int it = lane; it < cnt; it += 32) {
        int src = g * 256 + g_srcL[beg + it];
        float4 al = *(const float4*)&g_al[src * 4];
        float v0 = al.x + ar.x; v0 = (v0 > 0.f) ? v0 : 0.2f * v0;
        float v1 = al.y + ar.y; v1 = (v1 > 0.f) ? v1 : 0.2f * v1;
        float v2 = al.z + ar.z; v2 = (v2 > 0.f) ? v2 : 0.2f * v2;
        float v3 = al.w + ar.w; v3 = (v3 > 0.f) ? v3 : 0.2f * v3;
        float4 ev;
        ev.x = __expf(v0 - m0); ev.y = __expf(v1 - m1);
        ev.z = __expf(v2 - m2); ev.w = __expf(v3 - m3);
        *(float4*)&g_eeC[(beg + it) * 4] = ev;
        s0 += ev.x; s1 += ev.y; s2 += ev.z; s3 += ev.w;
    }
    #pragma unroll
    for (int o = 16; o > 0; o >>= 1) {
        s0 += __shfl_xor_sync(0xffffffffu, s0, o);
        s1 += __shfl_xor_sync(0xffffffffu, s1, o);
        s2 += __shfl_xor_sync(0xffffffffu, s2, o);
        s3 += __shfl_xor_sync(0xffffffffu, s3, o);
    }

    if (lane == 0) {
        float4 inv;
        inv.x = 1.f / (s0 + 1e-16f);
        inv.y = 1.f / (s1 + 1e-16f);
        inv.z = 1.f / (s2 + 1e-16f);
        inv.w = 1.f / (s3 + 1e-16f);
        *(float4*)&g_inv[node * 4] = inv;
    }
}

// ======================= onehot aggregation (gather form, smem-staged CSR) =======================
// grid = G*8 blocks; block covers (graph g, 32-col chunk); 256 thr = 32 dst x 8 f4
__global__ void k_ohagg(const float* __restrict__ oh, float* __restrict__ out) {
    __shared__ __align__(16) int s_src[4096];
    __shared__ int s_off[256];
    __shared__ int s_cnt[256];

    int g = blockIdx.x >> 3;
    int chunk = blockIdx.x & 7;
    int t = threadIdx.x;
    int q = t & 7;             // float4 within chunk
    int dsub = t >> 3;         // 0..31
    int colf4 = chunk * 8 + q; // 0..63

    // stage CSR for this graph
    {
        const int4* sp = (const int4*)&g_srcL[g * 4096];
        #pragma unroll
        for (int i = 0; i < 4; i++)
            *(int4*)&s_src[(t + i * 256) * 4] = sp[t + i * 256];
        s_off[t] = g_off[g * 256 + t];
        s_cnt[t] = g_cnt[g * 256 + t];
    }
    __syncthreads();

    const float4* ohg = (const float4*)(oh + (long long)g * 65536);
    float4* og = (float4*)(out + (long long)g * 65536);

    for (int d0 = 0; d0 < 256; d0 += 32) {
        int dst = d0 + dsub;
        float4 acc = ohg[dst * 64 + colf4];    // residual
        int beg = s_off[dst];
        int cnt = s_cnt[dst];
        int it = 0;
        for (; it + 4 <= cnt; it += 4) {
            int s0 = s_src[beg + it];
            int s1 = s_src[beg + it + 1];
            int s2 = s_src[beg + it + 2];
            int s3 = s_src[beg + it + 3];
            float4 v0 = ohg[s0 * 64 + colf4];
            float4 v1 = ohg[s1 * 64 + colf4];
            float4 v2 = ohg[s2 * 64 + colf4];
            float4 v3 = ohg[s3 * 64 + colf4];
            acc.x += v0.x + v1.x + v2.x + v3.x;
            acc.y += v0.y + v1.y + v2.y + v3.y;
            acc.z += v0.z + v1.z + v2.z + v3.z;
            acc.w += v0.w + v1.w + v2.w + v3.w;
        }
        for (; it < cnt; it++) {
            int srcl = s_src[beg + it];
            float4 v = ohg[srcl * 64 + colf4];
            acc.x += v.x; acc.y += v.y; acc.z += v.z; acc.w += v.w;
        }
        og[dst * 64 + colf4] = acc;
    }
}

// ======================= attention aggregation (gather form, smem-staged CSR) =======================
__global__ void k_attagg(float* __restrict__ out) {
    __shared__ __align__(16) int s_src[4096];
    __shared__ float s_w[4096];
    __shared__ int s_off[256];
    __shared__ int s_cnt[256];

    int g = blockIdx.x >> 3;
    int chunk = blockIdx.x & 7;
    int h = chunk >> 1;              // head = (chunk*32)/64
    int t = threadIdx.x;
    int q = t & 7;
    int dsub = t >> 3;
    int colf4 = chunk * 8 + q;       // float4 column 0..63

    // stage CSR + per-head weights for this graph
    {
        const int4* sp = (const int4*)&g_srcL[g * 4096];
        #pragma unroll
        for (int i = 0; i < 4; i++)
            *(int4*)&s_src[(t + i * 256) * 4] = sp[t + i * 256];
        #pragma unroll
        for (int i = 0; i < 16; i++)
            s_w[t + i * 256] = g_eeC[(g * 4096 + t + i * 256) * 4 + h];
        s_off[t] = g_off[g * 256 + t];
        s_cnt[t] = g_cnt[g * 256 + t];
    }
    __syncthreads();

    const float4* xpg = (const float4*)&g_xp[(long long)g * 256 * 256];

    for (int d0 = 0; d0 < 256; d0 += 32) {
        int dst = d0 + dsub;
        int node = g * 256 + dst;
        float inv = g_inv[node * 4 + h];
        float4 acc = {0.f, 0.f, 0.f, 0.f};
        int beg = s_off[dst];
        int cnt = s_cnt[dst];
        int it = 0;
        for (; it + 4 <= cnt; it += 4) {
            int s0 = s_src[beg + it];
            int s1 = s_src[beg + it + 1];
            int s2 = s_src[beg + it + 2];
            int s3 = s_src[beg + it + 3];
            float w0 = s_w[beg + it];
            float w1 = s_w[beg + it + 1];
            float w2 = s_w[beg + it + 2];
            float w3 = s_w[beg + it + 3];
            float4 v0 = xpg[s0 * 64 + colf4];
            float4 v1 = xpg[s1 * 64 + colf4];
            float4 v2 = xpg[s2 * 64 + colf4];
            float4 v3 = xpg[s3 * 64 + colf4];
            acc.x += w0 * v0.x + w1 * v1.x + w2 * v2.x + w3 * v3.x;
            acc.y += w0 * v0.y + w1 * v1.y + w2 * v2.y + w3 * v3.y;
            acc.z += w0 * v0.z + w1 * v1.z + w2 * v2.z + w3 * v3.z;
            acc.w += w0 * v0.w + w1 * v1.w + w2 * v2.w + w3 * v3.w;
        }
        for (; it < cnt; it++) {
            int srcl = s_src[beg + it];
            float w = s_w[beg + it];
            float4 v = xpg[srcl * 64 + colf4];
            acc.x += w * v.x; acc.y += w * v.y; acc.z += w * v.z; acc.w += w * v.w;
        }
        float4 b = *(const float4*)&g_wbias[colf4 * 4];
        acc.x = acc.x * inv + b.x;
        acc.y = acc.y * inv + b.y;
        acc.z = acc.z * inv + b.z;
        acc.w = acc.w * inv + b.w;
        *(float4*)&out[(long long)node * 256 + colf4 * 4] = acc;
    }
}

// ======================= launch =======================
extern "C" void kernel_launch(void* const* d_in, const int* in_sizes, int n_in,
                              void* d_out, int out_size) {
    const float* x    = (const float*)d_in[0];
    const float* oh   = (const float*)d_in[1];
    const int*   adjs = (const int*)d_in[2];       // int32 (JAX default x64-disabled)
    const float* lw   = (const float*)d_in[3];

    float* out   = (float*)d_out;
    float* x_out = out;                      // [N, 256]
    float* noh   = out + (size_t)NN * HC;    // [G, 256, 256]

    k_copyw<<<1, 256>>>((const float*)d_in[4], (const float*)d_in[5], (const float*)d_in[6],
                        (const float*)d_in[7], (const float*)d_in[8], (const float*)d_in[9],
                        (const float*)d_in[10], (const float*)d_in[11], (const float*)d_in[12]);
    k_csr     <<<G_, 256>>>(adjs);
    k_sortconv<<<NN, 256>>>(oh);
    k_gemm    <<<dim3(128, 2), 256>>>(x, lw);
    k_alpha   <<<256, 256>>>();
    k_softmax <<<NN / 8, 256>>>();           // 8 warps/block, one warp per node (4 heads/lane)
    k_ohagg   <<<512, 256>>>(oh, noh);
    k_attagg  <<<512, 256>>>(x_out);
}